// round 1
// baseline (speedup 1.0000x reference)
#include <cuda_runtime.h>
#include <mma.h>
#include <cstdint>

using namespace nvcuda;

#define B_    256
#define ATT_  196
#define RNN_  1024
#define INP_  1024

// ---------------- scratch (static device memory; no allocations) -------------
__device__ float g_V1[(size_t)B_ * ATT_ * ATT_];   // 50176 x 196
__device__ float g_V2[(size_t)B_ * ATT_ * ATT_];   // 50176 x 196
__device__ float g_ah1[B_ * ATT_];
__device__ float g_ah2[B_ * ATT_];
__device__ float g_dot[B_ * ATT_];
__device__ float g_w1[B_ * ATT_];
__device__ float g_w2[B_ * ATT_];
__device__ float g_S[B_ * 4 * RNN_];
__device__ float g_GA[B_ * 4 * RNN_];
__device__ float g_ares1[B_ * RNN_];

// ---------------- math helpers (accurate even under fast-math) ---------------
__device__ __forceinline__ float tanh_s(float x) {
    // 1 - 2/(e^{2x}+1): monotone, saturates cleanly to +/-1 at overflow/underflow
    return 1.0f - 2.0f / (expf(2.0f * x) + 1.0f);
}
__device__ __forceinline__ float sigmoid_s(float x) {
    return 1.0f / (1.0f + expf(-x));
}

// ---------------- tf32 wmma GEMM:  C[M,N] = A[M,K] * W[N,K]^T (+bias)(+=) ----
#define BM 128
#define BN 64
#define BK 16

__device__ __forceinline__ void cp_async16(float* smem_dst, const float* gmem_src) {
    uint32_t s = (uint32_t)__cvta_generic_to_shared(smem_dst);
    asm volatile("cp.async.cg.shared.global [%0], [%1], 16;" :: "r"(s), "l"(gmem_src));
}

__global__ __launch_bounds__(256) void gemm_tf32(
    const float* __restrict__ A, const float* __restrict__ W,
    const float* __restrict__ bias, float* __restrict__ C,
    int M, int N, int K, int accumulate)
{
    constexpr int CLD = BN + 4;
    // union: pipeline buffers (6144 floats) aliased with epilogue tile (8704 floats)
    __shared__ __align__(16) float sbuf[BM * CLD];
    float* As  = sbuf;                   // [2][BM*BK]
    float* Ws  = sbuf + 2 * BM * BK;     // [2][BN*BK]
    float* Cst = sbuf;                   // [BM][CLD]

    const int m0  = blockIdx.x * BM;
    const int n0  = blockIdx.y * BN;
    const int tid = threadIdx.x;
    const int warp = tid >> 5;
    const int wr = warp & 3;   // warp row 0..3 (32 rows each)
    const int wc = warp >> 2;  // warp col 0..1 (32 cols each)

    wmma::fragment<wmma::accumulator, 16, 16, 8, float> cf[2][2];
    #pragma unroll
    for (int i = 0; i < 2; i++)
        #pragma unroll
        for (int j = 0; j < 2; j++)
            wmma::fill_fragment(cf[i][j], 0.0f);

    const int ktiles = K / BK;

    auto load_tile = [&](int kt, int buf) {
        const int k0 = kt * BK;
        float* as = As + buf * (BM * BK);
        float* ws = Ws + buf * (BN * BK);
        // A tile: 128x16 floats = 512 float4, 256 threads x 2
        #pragma unroll
        for (int q = tid; q < (BM * BK) / 4; q += 256) {
            int row = q >> 2;
            int c4  = (q & 3) << 2;
            cp_async16(as + row * BK + c4, A + (size_t)(m0 + row) * K + k0 + c4);
        }
        // W tile: 64x16 floats = 256 float4, one per thread (zero-fill N edge)
        {
            int row = tid >> 2;
            int c4  = (tid & 3) << 2;
            float* dst = ws + row * BK + c4;
            if (n0 + row < N) {
                cp_async16(dst, W + (size_t)(n0 + row) * K + k0 + c4);
            } else {
                *(float4*)dst = make_float4(0.f, 0.f, 0.f, 0.f);
            }
        }
        asm volatile("cp.async.commit_group;");
    };

    load_tile(0, 0);
    for (int kt = 0; kt < ktiles; ++kt) {
        asm volatile("cp.async.wait_group 0;");
        __syncthreads();
        if (kt + 1 < ktiles) load_tile(kt + 1, (kt + 1) & 1);

        const float* as = As + (kt & 1) * (BM * BK);
        const float* ws = Ws + (kt & 1) * (BN * BK);
        #pragma unroll
        for (int ks = 0; ks < BK; ks += 8) {
            wmma::fragment<wmma::matrix_a, 16, 16, 8, wmma::precision::tf32, wmma::row_major> af[2];
            wmma::fragment<wmma::matrix_b, 16, 16, 8, wmma::precision::tf32, wmma::col_major> bf[2];
            #pragma unroll
            for (int i = 0; i < 2; i++) {
                wmma::load_matrix_sync(af[i], as + (wr * 32 + i * 16) * BK + ks, BK);
                #pragma unroll
                for (int e = 0; e < af[i].num_elements; e++)
                    af[i].x[e] = wmma::__float_to_tf32(af[i].x[e]);
            }
            #pragma unroll
            for (int j = 0; j < 2; j++) {
                wmma::load_matrix_sync(bf[j], ws + (wc * 32 + j * 16) * BK + ks, BK);
                #pragma unroll
                for (int e = 0; e < bf[j].num_elements; e++)
                    bf[j].x[e] = wmma::__float_to_tf32(bf[j].x[e]);
            }
            #pragma unroll
            for (int i = 0; i < 2; i++)
                #pragma unroll
                for (int j = 0; j < 2; j++)
                    wmma::mma_sync(cf[i][j], af[i], bf[j], cf[i][j]);
        }
    }

    __syncthreads();   // everyone done reading pipeline smem before Cst overwrite
    #pragma unroll
    for (int i = 0; i < 2; i++)
        #pragma unroll
        for (int j = 0; j < 2; j++)
            wmma::store_matrix_sync(Cst + (wr * 32 + i * 16) * CLD + (wc * 32 + j * 16),
                                    cf[i][j], CLD, wmma::mem_row_major);
    __syncthreads();

    for (int idx = tid; idx < BM * BN; idx += 256) {
        int r  = idx / BN;
        int c  = idx - r * BN;
        int gc = n0 + c;
        if (gc < N) {
            float v = Cst[r * CLD + c];
            if (bias) v += bias[gc];
            float* dst = C + (size_t)(m0 + r) * N + gc;
            if (accumulate) *dst += v;
            else            *dst = v;
        }
    }
}

// ---------------- dot[b,a] = sum_j Wd[j]*tanh(V[b*ATT+a, j] + ah[b*ATT+a]) ---
__global__ __launch_bounds__(256) void reduce_dot_kernel(
    const float* __restrict__ V, const float* __restrict__ ah,
    const float* __restrict__ Wd, const float* __restrict__ bd,
    float* __restrict__ dotv, int Mrows)
{
    int m    = (blockIdx.x * blockDim.x + threadIdx.x) >> 5;
    int lane = threadIdx.x & 31;
    if (m >= Mrows) return;
    float ahm = ah[m];
    const float* vr = V + (size_t)m * ATT_;
    float s = 0.f;
    #pragma unroll 2
    for (int j = lane; j < ATT_; j += 32)
        s += Wd[j] * tanh_s(vr[j] + ahm);
    #pragma unroll
    for (int o = 16; o; o >>= 1) s += __shfl_down_sync(0xffffffffu, s, o);
    if (lane == 0) dotv[m] = s + bd[0];
}

// ---------------- softmax over ATT per batch row ------------------------------
__global__ __launch_bounds__(256) void softmax_kernel(
    const float* __restrict__ dotv, float* __restrict__ w)
{
    int b = blockIdx.x;
    int t = threadIdx.x;
    __shared__ float sd[256];
    float v = (t < ATT_) ? dotv[b * ATT_ + t] : -1e30f;
    sd[t] = v; __syncthreads();
    #pragma unroll
    for (int s = 128; s; s >>= 1) { if (t < s) sd[t] = fmaxf(sd[t], sd[t + s]); __syncthreads(); }
    float mx = sd[0]; __syncthreads();
    float e = (t < ATT_) ? expf(v - mx) : 0.f;
    sd[t] = e; __syncthreads();
    #pragma unroll
    for (int s = 128; s; s >>= 1) { if (t < s) sd[t] += sd[t + s]; __syncthreads(); }
    float inv = 1.0f / sd[0];
    if (t < ATT_) w[b * ATT_ + t] = e * inv;
}

// ---------------- att_res[b,r] = sum_a att[b,a,r]*w[b,a]  (+ optional addend) -
__global__ __launch_bounds__(128) void attres_kernel(
    const float* __restrict__ att, const float* __restrict__ w,
    const float* __restrict__ addend, float* __restrict__ out)
{
    int b = blockIdx.x;
    int chunk = blockIdx.y;       // 0..1 (512 cols each)
    int t = threadIdx.x;          // 0..127
    __shared__ float ws[ATT_];
    for (int a = t; a < ATT_; a += 128) ws[a] = w[b * ATT_ + a];
    __syncthreads();
    int col = chunk * 512 + t * 4;
    const float4* base = (const float4*)(att + (size_t)b * ATT_ * RNN_ + col);
    float ax = 0.f, ay = 0.f, az = 0.f, aw = 0.f;
    #pragma unroll 4
    for (int a = 0; a < ATT_; ++a) {
        float4 v = base[(size_t)a * (RNN_ / 4)];
        float wa = ws[a];
        ax += wa * v.x; ay += wa * v.y; az += wa * v.z; aw += wa * v.w;
    }
    if (addend) {
        float4 q = *(const float4*)(addend + (size_t)b * RNN_ + col);
        ax += q.x; ay += q.y; az += q.z; aw += q.w;
    }
    *(float4*)(out + (size_t)b * RNN_ + col) = make_float4(ax, ay, az, aw);
}

// ---------------- LSTM gates -------------------------------------------------
__global__ __launch_bounds__(256) void gates_kernel(
    const float* __restrict__ S, const float* __restrict__ GA,
    const float* __restrict__ prev_c,
    float* __restrict__ next_c, float* __restrict__ next_h)
{
    int i = blockIdx.x * blockDim.x + threadIdx.x;   // < B*RNN
    int b = i >> 10, n = i & 1023;
    const float* s = S  + (size_t)b * 4 * RNN_;
    const float* g = GA + (size_t)b * 4 * RNN_;
    float si = s[n]            + g[n];
    float sf = s[RNN_ + n]     + g[RNN_ + n];
    float so = s[2 * RNN_ + n] + g[2 * RNN_ + n];
    float st = s[3 * RNN_ + n] + g[3 * RNN_ + n];
    float c = sigmoid_s(sf) * prev_c[i] + sigmoid_s(si) * tanh_s(st);
    float h = sigmoid_s(so) * tanh_s(c);
    next_c[i] = c;
    next_h[i] = h;
}

// ---------------- launcher ---------------------------------------------------
extern "C" void kernel_launch(void* const* d_in, const int* in_sizes, int n_in,
                              void* d_out, int out_size)
{
    const float* x      = (const float*)d_in[0];
    const float* att    = (const float*)d_in[1];
    const float* prev_h = (const float*)d_in[2];
    const float* prev_c = (const float*)d_in[3];
    const float* W_a2a  = (const float*)d_in[4];
    const float* b_a2a  = (const float*)d_in[5];
    const float* W_h2a  = (const float*)d_in[6];
    const float* b_h2a  = (const float*)d_in[7];
    const float* W_d2d  = (const float*)d_in[8];
    const float* b_d2d  = (const float*)d_in[9];
    const float* W_a2h  = (const float*)d_in[10];
    const float* b_a2h  = (const float*)d_in[11];
    const float* W_i2h  = (const float*)d_in[12];
    const float* b_i2h  = (const float*)d_in[13];
    const float* W_h2h  = (const float*)d_in[14];
    const float* b_h2h  = (const float*)d_in[15];
    const float* W_a2a1 = (const float*)d_in[16];
    const float* b_a2a1 = (const float*)d_in[17];
    const float* W_h2a1 = (const float*)d_in[18];
    const float* b_h2a1 = (const float*)d_in[19];
    const float* W_d2d1 = (const float*)d_in[20];
    const float* b_d2d1 = (const float*)d_in[21];

    float* out    = (float*)d_out;
    float* next_c = out;
    float* next_h = out + (size_t)B_ * RNN_;
    float* top_h  = out + (size_t)2 * B_ * RNN_;

    float *V1, *V2, *ah1, *ah2, *dotv, *w1, *w2, *S, *GA, *ares1;
    cudaGetSymbolAddress((void**)&V1,    g_V1);
    cudaGetSymbolAddress((void**)&V2,    g_V2);
    cudaGetSymbolAddress((void**)&ah1,   g_ah1);
    cudaGetSymbolAddress((void**)&ah2,   g_ah2);
    cudaGetSymbolAddress((void**)&dotv,  g_dot);
    cudaGetSymbolAddress((void**)&w1,    g_w1);
    cudaGetSymbolAddress((void**)&w2,    g_w2);
    cudaGetSymbolAddress((void**)&S,     g_S);
    cudaGetSymbolAddress((void**)&GA,    g_GA);
    cudaGetSymbolAddress((void**)&ares1, g_ares1);

    const int Mbig = B_ * ATT_;            // 50176
    const int NT196 = (ATT_ + BN - 1) / BN; // 4
    const int NT4096 = (4 * RNN_) / BN;     // 64

    // Phase A: everything independent of the h-chain
    gemm_tf32<<<dim3(Mbig / BM, NT196), 256>>>(att, W_a2a,  b_a2a,  V1, Mbig, ATT_, RNN_, 0);
    gemm_tf32<<<dim3(Mbig / BM, NT196), 256>>>(att, W_a2a1, b_a2a1, V2, Mbig, ATT_, RNN_, 0);
    gemm_tf32<<<dim3(B_ / BM, NT196), 256>>>(prev_h, W_h2a, b_h2a, ah1, B_, ATT_, RNN_, 0);
    gemm_tf32<<<dim3(B_ / BM, NT4096), 256>>>(x,      W_i2h, b_i2h, S, B_, 4 * RNN_, INP_, 0);
    gemm_tf32<<<dim3(B_ / BM, NT4096), 256>>>(prev_h, W_h2h, b_h2h, S, B_, 4 * RNN_, RNN_, 1);

    // Attend 1
    reduce_dot_kernel<<<Mbig / 8, 256>>>(V1, ah1, W_d2d, b_d2d, dotv, Mbig);
    softmax_kernel<<<B_, 256>>>(dotv, w1);
    attres_kernel<<<dim3(B_, 2), 128>>>(att, w1, nullptr, ares1);

    // LSTM
    gemm_tf32<<<dim3(B_ / BM, NT4096), 256>>>(ares1, W_a2h, b_a2h, GA, B_, 4 * RNN_, RNN_, 0);
    gates_kernel<<<(B_ * RNN_) / 256, 256>>>(S, GA, prev_c, next_c, next_h);

    // Attend 2 (on next_h)
    gemm_tf32<<<dim3(B_ / BM, NT196), 256>>>(next_h, W_h2a1, b_h2a1, ah2, B_, ATT_, RNN_, 0);
    reduce_dot_kernel<<<Mbig / 8, 256>>>(V2, ah2, W_d2d1, b_d2d1, dotv, Mbig);
    softmax_kernel<<<B_, 256>>>(dotv, w2);
    attres_kernel<<<dim3(B_, 2), 128>>>(att, w2, next_h, top_h);
}

// round 2
// speedup vs baseline: 1.1137x; 1.1137x over previous
#include <cuda_runtime.h>
#include <mma.h>
#include <cstdint>

using namespace nvcuda;

#define B_    256
#define ATT_  196
#define RNN_  1024
#define INP_  1024

#define BM 128
#define BN 64
#define BK 32
#define STAGES 3
#define LDA (BK + 4)     // 36: padded smem stride
#define CLD (BN + 4)     // 68: epilogue stride

// ---------------- scratch (static device memory; no allocations) -------------
__device__ float g_V1[(size_t)B_ * ATT_ * ATT_];   // 50176 x 196
__device__ float g_V2[(size_t)B_ * ATT_ * ATT_];   // 50176 x 196
__device__ float g_ah1[B_ * ATT_];
__device__ float g_ah2[B_ * ATT_];
__device__ float g_dot[B_ * ATT_];
__device__ float g_w1[B_ * ATT_];
__device__ float g_w2[B_ * ATT_];
__device__ float g_S[B_ * 4 * RNN_];
__device__ float g_ares1[B_ * RNN_];

// ---------------- math helpers (accurate even under fast-math) ---------------
__device__ __forceinline__ float tanh_s(float x) {
    return 1.0f - 2.0f / (expf(2.0f * x) + 1.0f);
}
__device__ __forceinline__ float sigmoid_s(float x) {
    return 1.0f / (1.0f + expf(-x));
}

// =============================================================================
// Generalized tf32 GEMM:
//   C[M, N1(+N2)] = concat_K(A0,A1,A2) @ concat_K(W0,W1,W2)^T   (+biases)
//   Columns [0,N1)      -> weights W0/W1/W2 (segmented K), output C0
//   Columns [N1,N1+N2)  -> weights Wn (nseg must be 1),    output Cn
// K is per-segment; all W are [Ncols x K] row-major.
// =============================================================================
__global__ __launch_bounds__(256, 2) void gemm_tf32k(
    const float* __restrict__ A0, const float* __restrict__ A1s, const float* __restrict__ A2s,
    const float* __restrict__ W0, const float* __restrict__ W1s, const float* __restrict__ W2s,
    const float* __restrict__ bias0a, const float* __restrict__ bias0b, const float* __restrict__ bias0c,
    float* __restrict__ C0, int N1,
    const float* __restrict__ Wn, const float* __restrict__ biasn, float* __restrict__ Cn, int N2,
    int M, int K, int nseg)
{
    extern __shared__ float smem[];
    float* As  = smem;                        // [STAGES][BM][LDA]
    float* Ws  = smem + STAGES * BM * LDA;    // [STAGES][BN][LDA]
    float* Cst = smem;                        // epilogue alias [BM][CLD]

    const int m0   = blockIdx.x * BM;
    const int n0   = blockIdx.y * BN;
    const int tid  = threadIdx.x;
    const int warp = tid >> 5;
    const int wr   = warp & 3;   // warp row (4 x 32 rows)
    const int wc   = warp >> 2;  // warp col (2 x 32 cols)

    const int kt_per_seg = K / BK;
    const int ktiles     = kt_per_seg * nseg;

    wmma::fragment<wmma::accumulator, 16, 16, 8, float> cf[2][2];
    #pragma unroll
    for (int i = 0; i < 2; i++)
        #pragma unroll
        for (int j = 0; j < 2; j++)
            wmma::fill_fragment(cf[i][j], 0.0f);

    auto load_tile = [&](int kt) {
        const int stage = kt % STAGES;
        const int seg   = (kt >= kt_per_seg) + (kt >= 2 * kt_per_seg);
        const int k0    = (kt - seg * kt_per_seg) * BK;
        const float* Ab = (seg == 0) ? A0 : (seg == 1) ? A1s : A2s;
        const float* Wb = (seg == 0) ? W0 : (seg == 1) ? W1s : W2s;
        float* as = As + stage * (BM * LDA);
        float* ws = Ws + stage * (BN * LDA);

        // A tile: 128 x 32 floats = 1024 float4 -> 4 per thread
        #pragma unroll
        for (int i = 0; i < 4; i++) {
            int q   = tid + i * 256;
            int row = q >> 3;
            int c4  = (q & 7) << 2;
            uint32_t s = (uint32_t)__cvta_generic_to_shared(as + row * LDA + c4);
            const float* g = Ab + (size_t)(m0 + row) * K + k0 + c4;
            asm volatile("cp.async.cg.shared.global [%0], [%1], 16;" :: "r"(s), "l"(g));
        }
        // W tile: 64 x 32 floats = 512 float4 -> 2 per thread (zfill N edge)
        #pragma unroll
        for (int i = 0; i < 2; i++) {
            int q   = tid + i * 256;
            int row = q >> 3;
            int c4  = (q & 7) << 2;
            int gc  = n0 + row;
            const float* g; int sz;
            if (gc < N1)           { g = Wb + (size_t)gc * K + k0 + c4;        sz = 16; }
            else if (gc < N1 + N2) { g = Wn + (size_t)(gc - N1) * K + k0 + c4; sz = 16; }
            else                   { g = Wb;                                    sz = 0;  }
            uint32_t s = (uint32_t)__cvta_generic_to_shared(ws + row * LDA + c4);
            asm volatile("cp.async.cg.shared.global [%0], [%1], 16, %2;" :: "r"(s), "l"(g), "r"(sz));
        }
        asm volatile("cp.async.commit_group;");
    };

    // prologue: 2 stages in flight
    load_tile(0);
    load_tile(1);

    for (int kt = 0; kt < ktiles; ++kt) {
        if (kt + 2 < ktiles) load_tile(kt + 2);
        else asm volatile("cp.async.commit_group;");     // keep group count uniform

        asm volatile("cp.async.wait_group %0;" :: "n"(STAGES - 1));
        __syncthreads();

        const float* as = As + (kt % STAGES) * (BM * LDA);
        const float* ws = Ws + (kt % STAGES) * (BN * LDA);
        #pragma unroll
        for (int ks = 0; ks < BK; ks += 8) {
            wmma::fragment<wmma::matrix_a, 16, 16, 8, wmma::precision::tf32, wmma::row_major> af[2];
            wmma::fragment<wmma::matrix_b, 16, 16, 8, wmma::precision::tf32, wmma::col_major> bf[2];
            #pragma unroll
            for (int i = 0; i < 2; i++) {
                wmma::load_matrix_sync(af[i], as + (wr * 32 + i * 16) * LDA + ks, LDA);
                #pragma unroll
                for (int e = 0; e < af[i].num_elements; e++)
                    af[i].x[e] = wmma::__float_to_tf32(af[i].x[e]);
            }
            #pragma unroll
            for (int j = 0; j < 2; j++) {
                wmma::load_matrix_sync(bf[j], ws + (wc * 32 + j * 16) * LDA + ks, LDA);
                #pragma unroll
                for (int e = 0; e < bf[j].num_elements; e++)
                    bf[j].x[e] = wmma::__float_to_tf32(bf[j].x[e]);
            }
            #pragma unroll
            for (int i = 0; i < 2; i++)
                #pragma unroll
                for (int j = 0; j < 2; j++)
                    wmma::mma_sync(cf[i][j], af[i], bf[j], cf[i][j]);
        }
        __syncthreads();   // stage reuse barrier (next iter overwrites this stage)
    }

    // epilogue via smem (aliases pipeline buffers; barrier above protects)
    #pragma unroll
    for (int i = 0; i < 2; i++)
        #pragma unroll
        for (int j = 0; j < 2; j++)
            wmma::store_matrix_sync(Cst + (wr * 32 + i * 16) * CLD + (wc * 32 + j * 16),
                                    cf[i][j], CLD, wmma::mem_row_major);
    __syncthreads();

    for (int idx = tid; idx < BM * BN; idx += 256) {
        int r  = idx >> 6;
        int c  = idx & (BN - 1);
        int gc = n0 + c;
        size_t m = m0 + r;
        float v = Cst[r * CLD + c];
        if (gc < N1) {
            if (bias0a) v += bias0a[gc];
            if (bias0b) v += bias0b[gc];
            if (bias0c) v += bias0c[gc];
            C0[m * N1 + gc] = v;
        } else if (gc < N1 + N2) {
            int g2 = gc - N1;
            if (biasn) v += biasn[g2];
            Cn[m * N2 + g2] = v;
        }
    }
}

// ---------------- dot[m] = bd + sum_j Wd[j]*tanh(V[m,j] + ah[m]) --------------
__global__ __launch_bounds__(256) void reduce_dot_kernel(
    const float* __restrict__ V, const float* __restrict__ ah,
    const float* __restrict__ Wd, const float* __restrict__ bd,
    float* __restrict__ dotv, int Mrows)
{
    int m    = (blockIdx.x * blockDim.x + threadIdx.x) >> 5;
    int lane = threadIdx.x & 31;
    if (m >= Mrows) return;
    float ahm = ah[m];
    const float* vr = V + (size_t)m * ATT_;
    float s = 0.f;
    #pragma unroll 2
    for (int j = lane; j < ATT_; j += 32)
        s += Wd[j] * tanh_s(vr[j] + ahm);
    #pragma unroll
    for (int o = 16; o; o >>= 1) s += __shfl_down_sync(0xffffffffu, s, o);
    if (lane == 0) dotv[m] = s + bd[0];
}

// ---------------- softmax over ATT per batch row ------------------------------
__global__ __launch_bounds__(256) void softmax_kernel(
    const float* __restrict__ dotv, float* __restrict__ w)
{
    int b = blockIdx.x;
    int t = threadIdx.x;
    __shared__ float sd[256];
    float v = (t < ATT_) ? dotv[b * ATT_ + t] : -1e30f;
    sd[t] = v; __syncthreads();
    #pragma unroll
    for (int s = 128; s; s >>= 1) { if (t < s) sd[t] = fmaxf(sd[t], sd[t + s]); __syncthreads(); }
    float mx = sd[0]; __syncthreads();
    float e = (t < ATT_) ? expf(v - mx) : 0.f;
    sd[t] = e; __syncthreads();
    #pragma unroll
    for (int s = 128; s; s >>= 1) { if (t < s) sd[t] += sd[t + s]; __syncthreads(); }
    float inv = 1.0f / sd[0];
    if (t < ATT_) w[b * ATT_ + t] = e * inv;
}

// ---------------- att_res[b,r] = sum_a att[b,a,r]*w[b,a] (+ optional addend) --
__global__ __launch_bounds__(128) void attres_kernel(
    const float* __restrict__ att, const float* __restrict__ w,
    const float* __restrict__ addend, float* __restrict__ out)
{
    int b = blockIdx.x;
    int t = threadIdx.x;          // 0..127 -> 8 floats each
    __shared__ float ws[ATT_];
    for (int a = t; a < ATT_; a += 128) ws[a] = w[b * ATT_ + a];
    __syncthreads();
    int col = t * 8;
    const float4* base = (const float4*)(att + (size_t)b * ATT_ * RNN_ + col);
    float4 s0 = make_float4(0.f, 0.f, 0.f, 0.f);
    float4 s1 = make_float4(0.f, 0.f, 0.f, 0.f);
    #pragma unroll 4
    for (int a = 0; a < ATT_; ++a) {
        float4 v0 = base[(size_t)a * (RNN_ / 4)];
        float4 v1 = base[(size_t)a * (RNN_ / 4) + 1];
        float wa = ws[a];
        s0.x += wa * v0.x; s0.y += wa * v0.y; s0.z += wa * v0.z; s0.w += wa * v0.w;
        s1.x += wa * v1.x; s1.y += wa * v1.y; s1.z += wa * v1.z; s1.w += wa * v1.w;
    }
    if (addend) {
        float4 q0 = *(const float4*)(addend + (size_t)b * RNN_ + col);
        float4 q1 = *(const float4*)(addend + (size_t)b * RNN_ + col + 4);
        s0.x += q0.x; s0.y += q0.y; s0.z += q0.z; s0.w += q0.w;
        s1.x += q1.x; s1.y += q1.y; s1.z += q1.z; s1.w += q1.w;
    }
    *(float4*)(out + (size_t)b * RNN_ + col)     = s0;
    *(float4*)(out + (size_t)b * RNN_ + col + 4) = s1;
}

// ---------------- LSTM gates (S already holds x·Wi + h·Wh + a·Wa + biases) ----
__global__ __launch_bounds__(256) void gates_kernel(
    const float* __restrict__ S, const float* __restrict__ prev_c,
    float* __restrict__ next_c, float* __restrict__ next_h)
{
    int i = blockIdx.x * blockDim.x + threadIdx.x;   // < B*RNN
    int b = i >> 10, n = i & 1023;
    const float* s = S + (size_t)b * 4 * RNN_;
    float si = s[n];
    float sf = s[RNN_ + n];
    float so = s[2 * RNN_ + n];
    float st = s[3 * RNN_ + n];
    float c = sigmoid_s(sf) * prev_c[i] + sigmoid_s(si) * tanh_s(st);
    float h = sigmoid_s(so) * tanh_s(c);
    next_c[i] = c;
    next_h[i] = h;
}

// ---------------- launcher ---------------------------------------------------
extern "C" void kernel_launch(void* const* d_in, const int* in_sizes, int n_in,
                              void* d_out, int out_size)
{
    const float* x      = (const float*)d_in[0];
    const float* att    = (const float*)d_in[1];
    const float* prev_h = (const float*)d_in[2];
    const float* prev_c = (const float*)d_in[3];
    const float* W_a2a  = (const float*)d_in[4];
    const float* b_a2a  = (const float*)d_in[5];
    const float* W_h2a  = (const float*)d_in[6];
    const float* b_h2a  = (const float*)d_in[7];
    const float* W_d2d  = (const float*)d_in[8];
    const float* b_d2d  = (const float*)d_in[9];
    const float* W_a2h  = (const float*)d_in[10];
    const float* b_a2h  = (const float*)d_in[11];
    const float* W_i2h  = (const float*)d_in[12];
    const float* b_i2h  = (const float*)d_in[13];
    const float* W_h2h  = (const float*)d_in[14];
    const float* b_h2h  = (const float*)d_in[15];
    const float* W_a2a1 = (const float*)d_in[16];
    const float* b_a2a1 = (const float*)d_in[17];
    const float* W_h2a1 = (const float*)d_in[18];
    const float* b_h2a1 = (const float*)d_in[19];
    const float* W_d2d1 = (const float*)d_in[20];
    const float* b_d2d1 = (const float*)d_in[21];

    float* out    = (float*)d_out;
    float* next_c = out;
    float* next_h = out + (size_t)B_ * RNN_;
    float* top_h  = out + (size_t)2 * B_ * RNN_;

    float *V1, *V2, *ah1, *ah2, *dotv, *w1, *w2, *S, *ares1;
    cudaGetSymbolAddress((void**)&V1,    g_V1);
    cudaGetSymbolAddress((void**)&V2,    g_V2);
    cudaGetSymbolAddress((void**)&ah1,   g_ah1);
    cudaGetSymbolAddress((void**)&ah2,   g_ah2);
    cudaGetSymbolAddress((void**)&dotv,  g_dot);
    cudaGetSymbolAddress((void**)&w1,    g_w1);
    cudaGetSymbolAddress((void**)&w2,    g_w2);
    cudaGetSymbolAddress((void**)&S,     g_S);
    cudaGetSymbolAddress((void**)&ares1, g_ares1);

    const int SMEM = STAGES * (BM + BN) * LDA * sizeof(float);   // 82944
    static int smem_set = 0;
    // idempotent attribute set (not a stream op; safe under capture)
    cudaFuncSetAttribute(gemm_tf32k, cudaFuncAttributeMaxDynamicSharedMemorySize, SMEM);
    (void)smem_set;

    const int Mbig = B_ * ATT_;            // 50176

    // 1) Fused big attention GEMM: [V1 | V2] = att @ [W_a2a | W_a2a1]^T
    gemm_tf32k<<<dim3(Mbig / BM, 7), 256, SMEM>>>(
        att, nullptr, nullptr,
        W_a2a, nullptr, nullptr,
        b_a2a, nullptr, nullptr,
        V1, ATT_,
        W_a2a1, b_a2a1, V2, ATT_,
        Mbig, RNN_, 1);

    // 2) ah1 = prev_h @ W_h2a^T
    gemm_tf32k<<<dim3(B_ / BM, 4), 256, SMEM>>>(
        prev_h, nullptr, nullptr,
        W_h2a, nullptr, nullptr,
        b_h2a, nullptr, nullptr,
        ah1, ATT_,
        nullptr, nullptr, nullptr, 0,
        B_, RNN_, 1);

    // 3) Attend 1
    reduce_dot_kernel<<<Mbig / 8, 256>>>(V1, ah1, W_d2d, b_d2d, dotv, Mbig);
    softmax_kernel<<<B_, 256>>>(dotv, w1);
    attres_kernel<<<B_, 128>>>(att, w1, nullptr, ares1);

    // 4) Fused LSTM sums: S = x@Wi^T + prev_h@Wh^T + ares1@Wa^T + biases
    gemm_tf32k<<<dim3(B_ / BM, (4 * RNN_) / BN), 256, SMEM>>>(
        x, prev_h, ares1,
        W_i2h, W_h2h, W_a2h,
        b_i2h, b_h2h, b_a2h,
        S, 4 * RNN_,
        nullptr, nullptr, nullptr, 0,
        B_, RNN_, 3);

    gates_kernel<<<(B_ * RNN_) / 256, 256>>>(S, prev_c, next_c, next_h);

    // 5) Attend 2 (on next_h)
    gemm_tf32k<<<dim3(B_ / BM, 4), 256, SMEM>>>(
        next_h, nullptr, nullptr,
        W_h2a1, nullptr, nullptr,
        b_h2a1, nullptr, nullptr,
        ah2, ATT_,
        nullptr, nullptr, nullptr, 0,
        B_, RNN_, 1);

    reduce_dot_kernel<<<Mbig / 8, 256>>>(V2, ah2, W_d2d1, b_d2d1, dotv, Mbig);
    softmax_kernel<<<B_, 256>>>(dotv, w2);
    attres_kernel<<<B_, 128>>>(att, w2, next_h, top_h);
}

// round 4
// speedup vs baseline: 2.9769x; 2.6731x over previous
#include <cuda_runtime.h>
#include <cuda_fp16.h>
#include <cstdint>

#define B_    256
#define ATT_  196
#define RNN_  1024
#define NBIG  392

#define BM 128
#define BN 64
#define BKH 64                 // halves per K-iter (128 bytes per row)
#define STAGES 3
#define GT 256
#define A_STAGE (BM * 128)     // 16384 B
#define B_STAGE (BN * 128)     // 8192 B
#define STAGE_BYTES (A_STAGE + B_STAGE)
#define GEMM_SMEM (STAGES * STAGE_BYTES)   // 73728 B
#define CLD 68

// ---------------- scratch (static device memory) -----------------------------
__device__ __half g_attH[(size_t)B_ * ATT_ * RNN_];   // 102.8 MB
__device__ __half g_V[(size_t)B_ * ATT_ * NBIG];      // fused [V1|V2], fp16
__device__ __half g_WbigH[NBIG * RNN_];
__device__ __half g_Wh2aH[ATT_ * RNN_];
__device__ __half g_Wh2a1H[ATT_ * RNN_];
__device__ __half g_Wi2hH[4 * RNN_ * RNN_];
__device__ __half g_Wh2hH[4 * RNN_ * RNN_];
__device__ __half g_Wa2hH[4 * RNN_ * RNN_];
__device__ __half g_xH[B_ * RNN_];
__device__ __half g_phH[B_ * RNN_];
__device__ __half g_ares1H[B_ * RNN_];
__device__ __half g_nhH[B_ * RNN_];
__device__ float  g_bbig[NBIG];
__device__ float  g_blstm[4 * RNN_];
__device__ float  g_ah1[B_ * ATT_];
__device__ float  g_ah2[B_ * ATT_];
__device__ float  g_dot[B_ * ATT_];
__device__ float  g_w1[B_ * ATT_];
__device__ float  g_w2[B_ * ATT_];
__device__ float  g_S[B_ * 4 * RNN_];
__device__ float  g_ares1[B_ * RNN_];

// ---------------- math helpers ------------------------------------------------
__device__ __forceinline__ float tanh_s(float x) {
    return 1.0f - 2.0f / (expf(2.0f * x) + 1.0f);
}
__device__ __forceinline__ float sigmoid_s(float x) {
    return 1.0f / (1.0f + expf(-x));
}
__device__ __forceinline__ uint32_t smem_u32(const void* p) {
    uint32_t a;
    asm("{ .reg .u64 t; cvta.to.shared.u64 t, %1; cvt.u32.u64 %0, t; }" : "=r"(a) : "l"(p));
    return a;
}
__device__ __forceinline__ void cp16(uint32_t dst, const void* src) {
    asm volatile("cp.async.cg.shared.global [%0], [%1], 16;" :: "r"(dst), "l"(src));
}
__device__ __forceinline__ void cp16z(uint32_t dst, const void* src, int sz) {
    asm volatile("cp.async.cg.shared.global [%0], [%1], 16, %2;" :: "r"(dst), "l"(src), "r"(sz));
}

#define LDSM4(R, addr)                                                          \
    asm volatile("ldmatrix.sync.aligned.m8n8.x4.shared.b16 {%0,%1,%2,%3}, [%4];" \
        : "=r"((R)[0]), "=r"((R)[1]), "=r"((R)[2]), "=r"((R)[3]) : "r"(addr))

#define MMA16816(C, A, B0v, B1v)                                                \
    asm volatile("mma.sync.aligned.m16n8k16.row.col.f32.f16.f16.f32 "           \
        "{%0,%1,%2,%3},{%4,%5,%6,%7},{%8,%9},{%0,%1,%2,%3};"                    \
        : "+f"((C)[0]), "+f"((C)[1]), "+f"((C)[2]), "+f"((C)[3])                 \
        : "r"((A)[0]), "r"((A)[1]), "r"((A)[2]), "r"((A)[3]), "r"(B0v), "r"(B1v))

// =============================================================================
// fp16 mma GEMM: C[M, Ntot] = sum_seg A_seg[M,K]h @ W_seg[N,K]h^T + bias
// BM=128, BN=64, BK=64 halves; 8 warps in 4(m) x 2(n); warp tile 32x32.
// grid: x = n-tile (fast), y = m-tile  -> wave shares A rows in L2.
// =============================================================================
extern __shared__ uint8_t smem_raw[];

__global__ __launch_bounds__(GT) void gemm_h16(
    const __half* __restrict__ A0, const __half* __restrict__ A1,
    const __half* __restrict__ A2,
    const __half* __restrict__ W0, const __half* __restrict__ W1,
    const __half* __restrict__ W2,
    const float* __restrict__ bias,
    __half* __restrict__ Ch, float* __restrict__ Cf, int ldc,
    int Ntot, int K, int nseg)
{
    const int tid  = threadIdx.x;
    const int lane = tid & 31;
    const int warp = tid >> 5;
    const int wm   = warp & 3;
    const int wn   = warp >> 2;
    const int n0   = blockIdx.x * BN;
    const int m0   = blockIdx.y * BM;

    const uint32_t sbase = smem_u32(smem_raw);
    const int kt_per_seg = K / BKH;
    const int ktotal     = kt_per_seg * nseg;

    auto load_stage = [&](int l) {
        const int s   = l % STAGES;
        const int seg = (nseg > 1) ? (l / kt_per_seg) : 0;
        const int kk  = (l - seg * kt_per_seg) * BKH;   // halves
        const __half* Ab = (seg == 0) ? A0 : (seg == 1) ? A1 : A2;
        const __half* Wb = (seg == 0) ? W0 : (seg == 1) ? W1 : W2;
        const uint32_t abase = sbase + s * STAGE_BYTES;
        const uint32_t bbase = abase + A_STAGE;
        #pragma unroll
        for (int i = 0; i < 4; i++) {                    // A: 1024 chunks
            int q = tid + i * GT;
            int row = q >> 3, c = q & 7;
            uint32_t dst = abase + row * 128 + ((c ^ (row & 7)) << 4);
            cp16(dst, Ab + (size_t)(m0 + row) * K + kk + c * 8);
        }
        #pragma unroll
        for (int i = 0; i < 2; i++) {                    // B: 512 chunks
            int q = tid + i * GT;
            int row = q >> 3, c = q & 7;
            int gr = n0 + row;
            uint32_t dst = bbase + row * 128 + ((c ^ (row & 7)) << 4);
            const __half* src; int sz;
            if (gr < Ntot) { src = Wb + (size_t)gr * K + kk + c * 8; sz = 16; }
            else           { src = Wb;                               sz = 0;  }
            cp16z(dst, src, sz);
        }
        asm volatile("cp.async.commit_group;" ::: "memory");
    };

    float acc[2][4][4] = {};

    // ldmatrix per-thread address constants
    const int laneRow = lane & 7;
    const int m8      = (lane >> 3) & 1;   // A: row +8 for matrices 1,3
    const int cAdd    = lane >> 4;         // A: chunk +1 for matrices 2,3
    const uint32_t aOff0 = (uint32_t)(wm * 32 + m8 * 8 + laneRow) * 128;
    const uint32_t aOff1 = aOff0 + 16 * 128;
    const uint32_t bOff  = (uint32_t)(wn * 32 + (lane >> 3) * 8 + laneRow) * 128;

    load_stage(0);
    load_stage(1);

    for (int kt = 0; kt < ktotal; ++kt) {
        if (kt + 2 < ktotal) load_stage(kt + 2);
        else asm volatile("cp.async.commit_group;" ::: "memory");
        asm volatile("cp.async.wait_group %0;" :: "n"(STAGES - 1));
        __syncthreads();

        const uint32_t abase = sbase + (kt % STAGES) * STAGE_BYTES;
        const uint32_t bbase = abase + A_STAGE;
        #pragma unroll
        for (int ks = 0; ks < 4; ++ks) {
            uint32_t a[2][4], b0[4], b1[4];
            uint32_t aSw = (uint32_t)(((2 * ks + cAdd) ^ laneRow) << 4);
            LDSM4(a[0], abase + aOff0 + aSw);
            LDSM4(a[1], abase + aOff1 + aSw);
            LDSM4(b0, bbase + bOff + (uint32_t)(((2 * ks)     ^ laneRow) << 4));
            LDSM4(b1, bbase + bOff + (uint32_t)(((2 * ks + 1) ^ laneRow) << 4));
            #pragma unroll
            for (int f = 0; f < 2; f++)
                #pragma unroll
                for (int j = 0; j < 4; j++)
                    MMA16816(acc[f][j], a[f], b0[j], b1[j]);
        }
        __syncthreads();
    }

    // epilogue via smem bounce (aliases pipeline stages; loop's trailing sync protects)
    float* Cst = (float*)smem_raw;
    #pragma unroll
    for (int f = 0; f < 2; f++)
        #pragma unroll
        for (int j = 0; j < 4; j++) {
            int r0 = wm * 32 + f * 16 + (lane >> 2);
            int c0 = wn * 32 + j * 8 + (lane & 3) * 2;
            Cst[r0 * CLD + c0]           = acc[f][j][0];
            Cst[r0 * CLD + c0 + 1]       = acc[f][j][1];
            Cst[(r0 + 8) * CLD + c0]     = acc[f][j][2];
            Cst[(r0 + 8) * CLD + c0 + 1] = acc[f][j][3];
        }
    __syncthreads();

    for (int idx = tid; idx < BM * BN; idx += GT) {
        int r = idx >> 6, c = idx & 63, gc = n0 + c;
        if (gc < Ntot) {
            float v = Cst[r * CLD + c] + (bias ? bias[gc] : 0.f);
            if (Ch) Ch[(size_t)(m0 + r) * ldc + gc] = __float2half(v);
            else    Cf[(size_t)(m0 + r) * ldc + gc] = v;
        }
    }
}

// ---------------- f32 -> f16 convert -----------------------------------------
__global__ __launch_bounds__(256) void f2h_kernel(
    const float* __restrict__ in, __half* __restrict__ out, int n4)
{
    int i = blockIdx.x * blockDim.x + threadIdx.x;
    if (i < n4) {
        float4 v = ((const float4*)in)[i];
        __half2 h0 = __floats2half2_rn(v.x, v.y);
        __half2 h1 = __floats2half2_rn(v.z, v.w);
        ((__half2*)out)[2 * i]     = h0;
        ((__half2*)out)[2 * i + 1] = h1;
    }
}

// ---------------- bias fusions -----------------------------------------------
__global__ void bias_cat2_kernel(const float* a, const float* b, float* o) {
    int t = threadIdx.x;
    if (t < ATT_) o[t] = a[t];
    else if (t < NBIG) o[t] = b[t - ATT_];
}
__global__ void bias_sum3_kernel(const float* a, const float* b, const float* c,
                                 float* o) {
    int i = blockIdx.x * blockDim.x + threadIdx.x;
    o[i] = a[i] + b[i] + c[i];
}

// ---------------- dot[m] = bd + sum_j Wd[j]*tanh(V[m,j] + ah[m]) -------------
__global__ __launch_bounds__(256) void reduce_dot_kernel(
    const __half* __restrict__ V, int ldv, const float* __restrict__ ah,
    const float* __restrict__ Wd, const float* __restrict__ bd,
    float* __restrict__ dotv, int Mrows)
{
    int m    = (blockIdx.x * blockDim.x + threadIdx.x) >> 5;
    int lane = threadIdx.x & 31;
    if (m >= Mrows) return;
    float ahm = ah[m];
    const __half* vr = V + (size_t)m * ldv;
    float s = 0.f;
    #pragma unroll 2
    for (int j = lane; j < ATT_; j += 32)
        s += Wd[j] * tanh_s(__half2float(vr[j]) + ahm);
    #pragma unroll
    for (int o = 16; o; o >>= 1) s += __shfl_down_sync(0xffffffffu, s, o);
    if (lane == 0) dotv[m] = s + bd[0];
}

// ---------------- softmax over ATT per batch row -----------------------------
__global__ __launch_bounds__(256) void softmax_kernel(
    const float* __restrict__ dotv, float* __restrict__ w)
{
    int b = blockIdx.x;
    int t = threadIdx.x;
    __shared__ float sd[256];
    float v = (t < ATT_) ? dotv[b * ATT_ + t] : -1e30f;
    sd[t] = v; __syncthreads();
    #pragma unroll
    for (int s = 128; s; s >>= 1) { if (t < s) sd[t] = fmaxf(sd[t], sd[t + s]); __syncthreads(); }
    float mx = sd[0]; __syncthreads();
    float e = (t < ATT_) ? expf(v - mx) : 0.f;
    sd[t] = e; __syncthreads();
    #pragma unroll
    for (int s = 128; s; s >>= 1) { if (t < s) sd[t] += sd[t + s]; __syncthreads(); }
    float inv = 1.0f / sd[0];
    if (t < ATT_) w[b * ATT_ + t] = e * inv;
}

// ---------------- att_res[b,r] = sum_a attH[b,a,r]*w[b,a] (+ addend) ---------
__global__ __launch_bounds__(128) void attres_kernel(
    const __half* __restrict__ attH, const float* __restrict__ w,
    const float* __restrict__ addend, float* __restrict__ out)
{
    int b = blockIdx.x;
    int t = threadIdx.x;
    __shared__ float ws[ATT_];
    for (int a = t; a < ATT_; a += 128) ws[a] = w[b * ATT_ + a];
    __syncthreads();
    int col = t * 8;
    const uint4* base = (const uint4*)(attH + (size_t)b * ATT_ * RNN_ + col);
    float s[8] = {};
    #pragma unroll 4
    for (int a = 0; a < ATT_; ++a) {
        uint4 u = base[(size_t)a * (RNN_ / 8)];
        const __half2* hp = (const __half2*)&u;
        float wa = ws[a];
        #pragma unroll
        for (int q = 0; q < 4; q++) {
            float2 f = __half22float2(hp[q]);
            s[2 * q]     += wa * f.x;
            s[2 * q + 1] += wa * f.y;
        }
    }
    if (addend) {
        #pragma unroll
        for (int q = 0; q < 8; q++) s[q] += addend[(size_t)b * RNN_ + col + q];
    }
    #pragma unroll
    for (int q = 0; q < 8; q += 4)
        *(float4*)(out + (size_t)b * RNN_ + col + q) =
            make_float4(s[q], s[q + 1], s[q + 2], s[q + 3]);
}

// ---------------- LSTM gates --------------------------------------------------
__global__ __launch_bounds__(256) void gates_kernel(
    const float* __restrict__ S, const float* __restrict__ prev_c,
    float* __restrict__ next_c, float* __restrict__ next_h)
{
    int i = blockIdx.x * blockDim.x + threadIdx.x;
    int b = i >> 10, n = i & 1023;
    const float* s = S + (size_t)b * 4 * RNN_;
    float si = s[n];
    float sf = s[RNN_ + n];
    float so = s[2 * RNN_ + n];
    float st = s[3 * RNN_ + n];
    float c = sigmoid_s(sf) * prev_c[i] + sigmoid_s(si) * tanh_s(st);
    float h = sigmoid_s(so) * tanh_s(c);
    next_c[i] = c;
    next_h[i] = h;
}

// ---------------- launcher ----------------------------------------------------
extern "C" void kernel_launch(void* const* d_in, const int* in_sizes, int n_in,
                              void* d_out, int out_size)
{
    const float* x      = (const float*)d_in[0];
    const float* att    = (const float*)d_in[1];
    const float* prev_h = (const float*)d_in[2];
    const float* prev_c = (const float*)d_in[3];
    const float* W_a2a  = (const float*)d_in[4];
    const float* b_a2a  = (const float*)d_in[5];
    const float* W_h2a  = (const float*)d_in[6];
    const float* b_h2a  = (const float*)d_in[7];
    const float* W_d2d  = (const float*)d_in[8];
    const float* b_d2d  = (const float*)d_in[9];
    const float* W_a2h  = (const float*)d_in[10];
    const float* b_a2h  = (const float*)d_in[11];
    const float* W_i2h  = (const float*)d_in[12];
    const float* b_i2h  = (const float*)d_in[13];
    const float* W_h2h  = (const float*)d_in[14];
    const float* b_h2h  = (const float*)d_in[15];
    const float* W_a2a1 = (const float*)d_in[16];
    const float* b_a2a1 = (const float*)d_in[17];
    const float* W_h2a1 = (const float*)d_in[18];
    const float* b_h2a1 = (const float*)d_in[19];
    const float* W_d2d1 = (const float*)d_in[20];
    const float* b_d2d1 = (const float*)d_in[21];

    float* out    = (float*)d_out;
    float* next_c = out;
    float* next_h = out + (size_t)B_ * RNN_;
    float* top_h  = out + (size_t)2 * B_ * RNN_;

    __half *attH, *V, *WbigH, *Wh2aH, *Wh2a1H, *Wi2hH, *Wh2hH, *Wa2hH;
    __half *xH, *phH, *ares1H, *nhH;
    float *bbig, *blstm, *ah1, *ah2, *dotv, *w1, *w2, *S, *ares1;
    cudaGetSymbolAddress((void**)&attH,   g_attH);
    cudaGetSymbolAddress((void**)&V,      g_V);
    cudaGetSymbolAddress((void**)&WbigH,  g_WbigH);
    cudaGetSymbolAddress((void**)&Wh2aH,  g_Wh2aH);
    cudaGetSymbolAddress((void**)&Wh2a1H, g_Wh2a1H);
    cudaGetSymbolAddress((void**)&Wi2hH,  g_Wi2hH);
    cudaGetSymbolAddress((void**)&Wh2hH,  g_Wh2hH);
    cudaGetSymbolAddress((void**)&Wa2hH,  g_Wa2hH);
    cudaGetSymbolAddress((void**)&xH,     g_xH);
    cudaGetSymbolAddress((void**)&phH,    g_phH);
    cudaGetSymbolAddress((void**)&ares1H, g_ares1H);
    cudaGetSymbolAddress((void**)&nhH,    g_nhH);
    cudaGetSymbolAddress((void**)&bbig,   g_bbig);
    cudaGetSymbolAddress((void**)&blstm,  g_blstm);
    cudaGetSymbolAddress((void**)&ah1,    g_ah1);
    cudaGetSymbolAddress((void**)&ah2,    g_ah2);
    cudaGetSymbolAddress((void**)&dotv,   g_dot);
    cudaGetSymbolAddress((void**)&w1,     g_w1);
    cudaGetSymbolAddress((void**)&w2,     g_w2);
    cudaGetSymbolAddress((void**)&S,      g_S);
    cudaGetSymbolAddress((void**)&ares1,  g_ares1);

    cudaFuncSetAttribute(gemm_h16, cudaFuncAttributeMaxDynamicSharedMemorySize,
                         GEMM_SMEM);

    const int Mbig = B_ * ATT_;   // 50176
    const int BV   = B_ * RNN_;   // 262144

    // ---- converts (inputs + weights) ----
    f2h_kernel<<<(Mbig * RNN_ / 4 + 255) / 256, 256>>>(att, attH, Mbig * RNN_ / 4);
    f2h_kernel<<<BV / 4 / 256, 256>>>(x,      xH,  BV / 4);
    f2h_kernel<<<BV / 4 / 256, 256>>>(prev_h, phH, BV / 4);
    f2h_kernel<<<ATT_ * RNN_ / 4 / 256, 256>>>(W_a2a,  WbigH,              ATT_ * RNN_ / 4);
    f2h_kernel<<<ATT_ * RNN_ / 4 / 256, 256>>>(W_a2a1, WbigH + ATT_ * RNN_, ATT_ * RNN_ / 4);
    f2h_kernel<<<ATT_ * RNN_ / 4 / 256, 256>>>(W_h2a,  Wh2aH,  ATT_ * RNN_ / 4);
    f2h_kernel<<<ATT_ * RNN_ / 4 / 256, 256>>>(W_h2a1, Wh2a1H, ATT_ * RNN_ / 4);
    f2h_kernel<<<4 * RNN_ * RNN_ / 4 / 256, 256>>>(W_i2h, Wi2hH, RNN_ * RNN_);
    f2h_kernel<<<4 * RNN_ * RNN_ / 4 / 256, 256>>>(W_h2h, Wh2hH, RNN_ * RNN_);
    f2h_kernel<<<4 * RNN_ * RNN_ / 4 / 256, 256>>>(W_a2h, Wa2hH, RNN_ * RNN_);
    bias_cat2_kernel<<<1, 512>>>(b_a2a, b_a2a1, bbig);
    bias_sum3_kernel<<<4 * RNN_ / 256, 256>>>(b_i2h, b_h2h, b_a2h, blstm);

    // ---- 1) fused big attention GEMM: V[:,0:392] = attH @ WbigH^T ----
    gemm_h16<<<dim3(7, Mbig / BM), GT, GEMM_SMEM>>>(
        attH, nullptr, nullptr, WbigH, nullptr, nullptr,
        bbig, V, nullptr, NBIG, NBIG, RNN_, 1);

    // ---- 2) ah1 = prev_h @ W_h2a^T ----
    gemm_h16<<<dim3(4, B_ / BM), GT, GEMM_SMEM>>>(
        phH, nullptr, nullptr, Wh2aH, nullptr, nullptr,
        b_h2a, nullptr, ah1, ATT_, ATT_, RNN_, 1);

    // ---- 3) attend 1 ----
    reduce_dot_kernel<<<Mbig / 8, 256>>>(V, NBIG, ah1, W_d2d, b_d2d, dotv, Mbig);
    softmax_kernel<<<B_, 256>>>(dotv, w1);
    attres_kernel<<<B_, 128>>>(attH, w1, nullptr, ares1);
    f2h_kernel<<<BV / 4 / 256, 256>>>(ares1, ares1H, BV / 4);

    // ---- 4) fused LSTM: S = xH@Wi^T + phH@Wh^T + ares1H@Wa^T + blstm ----
    gemm_h16<<<dim3(64, B_ / BM), GT, GEMM_SMEM>>>(
        xH, phH, ares1H, Wi2hH, Wh2hH, Wa2hH,
        blstm, nullptr, S, 4 * RNN_, 4 * RNN_, RNN_, 3);

    gates_kernel<<<(B_ * RNN_) / 256, 256>>>(S, prev_c, next_c, next_h);
    f2h_kernel<<<BV / 4 / 256, 256>>>(next_h, nhH, BV / 4);

    // ---- 5) attend 2 (on next_h) ----
    gemm_h16<<<dim3(4, B_ / BM), GT, GEMM_SMEM>>>(
        nhH, nullptr, nullptr, Wh2a1H, nullptr, nullptr,
        b_h2a1, nullptr, ah2, ATT_, ATT_, RNN_, 1);

    reduce_dot_kernel<<<Mbig / 8, 256>>>(V + ATT_, NBIG, ah2, W_d2d1, b_d2d1, dotv, Mbig);
    softmax_kernel<<<B_, 256>>>(dotv, w2);
    attres_kernel<<<B_, 128>>>(attH, w2, next_h, top_h);
}

// round 5
// speedup vs baseline: 2.9877x; 1.0036x over previous
#include <cuda_runtime.h>
#include <cuda_fp16.h>
#include <cstdint>

#define B_    256
#define ATT_  196
#define RNN_  1024
#define NBIG  392

#define GT 256
#define STAGES 3
#define CLD 68

// ---- small gemm (BM=128) geometry ----
#define BM 128
#define BN 64
#define A_STAGE (BM * 128)
#define B_STAGE (BN * 128)
#define STAGE_BYTES (A_STAGE + B_STAGE)
#define GEMM_SMEM (STAGES * STAGE_BYTES)          // 73728

// ---- big gemm (BM=256) geometry ----
#define BM2 256
#define A_STAGE2 (BM2 * 128)
#define STAGE_BYTES2 (A_STAGE2 + B_STAGE)
#define GEMM_SMEM2 (STAGES * STAGE_BYTES2)        // 122880

// ---------------- fp16 arena (single buffer, 8-half-aligned segments) --------
#define SZ_ATT   ((size_t)B_ * ATT_ * RNN_)       // 51,380,224
#define SZ_BV    ((size_t)B_ * RNN_)              // 262,144
#define SZ_WATT  ((size_t)ATT_ * RNN_)            // 200,704
#define SZ_WL    ((size_t)4 * RNN_ * RNN_)        // 4,194,304

#define OFF_ATT    ((size_t)0)
#define OFF_X      (OFF_ATT   + SZ_ATT)
#define OFF_PH     (OFF_X     + SZ_BV)
#define OFF_WBIG   (OFF_PH    + SZ_BV)            // W_a2a | W_a2a1
#define OFF_WH2A   (OFF_WBIG  + 2 * SZ_WATT)
#define OFF_WH2A1  (OFF_WH2A  + SZ_WATT)
#define OFF_WI2H   (OFF_WH2A1 + SZ_WATT)
#define OFF_WH2H   (OFF_WI2H  + SZ_WL)
#define OFF_WA2H   (OFF_WH2H  + SZ_WL)
#define OFF_ARES1  (OFF_WA2H  + SZ_WL)
#define OFF_NH     (OFF_ARES1 + SZ_BV)
#define ARENA_SZ   (OFF_NH    + SZ_BV)

__device__ __half g_h[ARENA_SZ];
__device__ __half g_V[(size_t)B_ * ATT_ * NBIG];
__device__ float  g_bbig[NBIG];
__device__ float  g_blstm[4 * RNN_];
__device__ float  g_ah1[B_ * ATT_];
__device__ float  g_ah2[B_ * ATT_];
__device__ float  g_dot[B_ * ATT_];
__device__ float  g_w1[B_ * ATT_];
__device__ float  g_w2[B_ * ATT_];
__device__ float  g_S[B_ * 4 * RNN_];

// ---------------- math helpers ------------------------------------------------
__device__ __forceinline__ float tanh_s(float x) {
    return 1.0f - 2.0f / (expf(2.0f * x) + 1.0f);
}
__device__ __forceinline__ float sigmoid_s(float x) {
    return 1.0f / (1.0f + expf(-x));
}
__device__ __forceinline__ uint32_t smem_u32(const void* p) {
    uint32_t a;
    asm("{ .reg .u64 t; cvta.to.shared.u64 t, %1; cvt.u32.u64 %0, t; }" : "=r"(a) : "l"(p));
    return a;
}
__device__ __forceinline__ void cp16(uint32_t dst, const void* src) {
    asm volatile("cp.async.cg.shared.global [%0], [%1], 16;" :: "r"(dst), "l"(src));
}
__device__ __forceinline__ void cp16z(uint32_t dst, const void* src, int sz) {
    asm volatile("cp.async.cg.shared.global [%0], [%1], 16, %2;" :: "r"(dst), "l"(src), "r"(sz));
}

#define LDSM4(R, addr)                                                          \
    asm volatile("ldmatrix.sync.aligned.m8n8.x4.shared.b16 {%0,%1,%2,%3}, [%4];" \
        : "=r"((R)[0]), "=r"((R)[1]), "=r"((R)[2]), "=r"((R)[3]) : "r"(addr))

#define MMA16816(C, A, B0v, B1v)                                                \
    asm volatile("mma.sync.aligned.m16n8k16.row.col.f32.f16.f16.f32 "           \
        "{%0,%1,%2,%3},{%4,%5,%6,%7},{%8,%9},{%0,%1,%2,%3};"                    \
        : "+f"((C)[0]), "+f"((C)[1]), "+f"((C)[2]), "+f"((C)[3])                 \
        : "r"((A)[0]), "r"((A)[1]), "r"((A)[2]), "r"((A)[3]), "r"(B0v), "r"(B1v))

extern __shared__ uint8_t smem_raw[];

// =============================================================================
// small fp16 GEMM: BM=128, BN=64, 8 warps 4(m)x2(n), warp tile 32x32
// =============================================================================
__global__ __launch_bounds__(GT) void gemm_h16(
    const __half* __restrict__ A0, const __half* __restrict__ A1,
    const __half* __restrict__ A2,
    const __half* __restrict__ W0, const __half* __restrict__ W1,
    const __half* __restrict__ W2,
    const float* __restrict__ bias,
    __half* __restrict__ Ch, float* __restrict__ Cf, int ldc,
    int Ntot, int K, int nseg)
{
    const int tid  = threadIdx.x;
    const int lane = tid & 31;
    const int warp = tid >> 5;
    const int wm   = warp & 3;
    const int wn   = warp >> 2;
    const int n0   = blockIdx.x * BN;
    const int m0   = blockIdx.y * BM;

    const uint32_t sbase = smem_u32(smem_raw);
    const int kt_per_seg = K / 64;
    const int ktotal     = kt_per_seg * nseg;

    auto load_stage = [&](int l) {
        const int s   = l % STAGES;
        const int seg = (nseg > 1) ? (l / kt_per_seg) : 0;
        const int kk  = (l - seg * kt_per_seg) * 64;
        const __half* Ab = (seg == 0) ? A0 : (seg == 1) ? A1 : A2;
        const __half* Wb = (seg == 0) ? W0 : (seg == 1) ? W1 : W2;
        const uint32_t abase = sbase + s * STAGE_BYTES;
        const uint32_t bbase = abase + A_STAGE;
        #pragma unroll
        for (int i = 0; i < 4; i++) {
            int q = tid + i * GT;
            int row = q >> 3, c = q & 7;
            cp16(abase + row * 128 + ((c ^ (row & 7)) << 4),
                 Ab + (size_t)(m0 + row) * K + kk + c * 8);
        }
        #pragma unroll
        for (int i = 0; i < 2; i++) {
            int q = tid + i * GT;
            int row = q >> 3, c = q & 7;
            int gr = n0 + row;
            const __half* src; int sz;
            if (gr < Ntot) { src = Wb + (size_t)gr * K + kk + c * 8; sz = 16; }
            else           { src = Wb;                               sz = 0;  }
            cp16z(bbase + row * 128 + ((c ^ (row & 7)) << 4), src, sz);
        }
        asm volatile("cp.async.commit_group;" ::: "memory");
    };

    float acc[2][4][4] = {};
    const int laneRow = lane & 7;
    const int m8      = (lane >> 3) & 1;
    const int cAdd    = lane >> 4;
    const uint32_t aOff0 = (uint32_t)(wm * 32 + m8 * 8 + laneRow) * 128;
    const uint32_t aOff1 = aOff0 + 16 * 128;
    const uint32_t bOff  = (uint32_t)(wn * 32 + (lane >> 3) * 8 + laneRow) * 128;

    load_stage(0);
    load_stage(1);

    for (int kt = 0; kt < ktotal; ++kt) {
        if (kt + 2 < ktotal) load_stage(kt + 2);
        else asm volatile("cp.async.commit_group;" ::: "memory");
        asm volatile("cp.async.wait_group %0;" :: "n"(STAGES - 1));
        __syncthreads();

        const uint32_t abase = sbase + (kt % STAGES) * STAGE_BYTES;
        const uint32_t bbase = abase + A_STAGE;
        #pragma unroll
        for (int ks = 0; ks < 4; ++ks) {
            uint32_t a[2][4], b0[4], b1[4];
            uint32_t aSw = (uint32_t)(((2 * ks + cAdd) ^ laneRow) << 4);
            LDSM4(a[0], abase + aOff0 + aSw);
            LDSM4(a[1], abase + aOff1 + aSw);
            LDSM4(b0, bbase + bOff + (uint32_t)(((2 * ks)     ^ laneRow) << 4));
            LDSM4(b1, bbase + bOff + (uint32_t)(((2 * ks + 1) ^ laneRow) << 4));
            #pragma unroll
            for (int f = 0; f < 2; f++)
                #pragma unroll
                for (int j = 0; j < 4; j++)
                    MMA16816(acc[f][j], a[f], b0[j], b1[j]);
        }
        __syncthreads();
    }

    float* Cst = (float*)smem_raw;
    #pragma unroll
    for (int f = 0; f < 2; f++)
        #pragma unroll
        for (int j = 0; j < 4; j++) {
            int r0 = wm * 32 + f * 16 + (lane >> 2);
            int c0 = wn * 32 + j * 8 + (lane & 3) * 2;
            Cst[r0 * CLD + c0]           = acc[f][j][0];
            Cst[r0 * CLD + c0 + 1]       = acc[f][j][1];
            Cst[(r0 + 8) * CLD + c0]     = acc[f][j][2];
            Cst[(r0 + 8) * CLD + c0 + 1] = acc[f][j][3];
        }
    __syncthreads();

    for (int idx = tid; idx < BM * BN; idx += GT) {
        int r = idx >> 6, c = idx & 63, gc = n0 + c;
        if (gc < Ntot) {
            float v = Cst[r * CLD + c] + (bias ? bias[gc] : 0.f);
            if (Ch) Ch[(size_t)(m0 + r) * ldc + gc] = __float2half(v);
            else    Cf[(size_t)(m0 + r) * ldc + gc] = v;
        }
    }
}

// =============================================================================
// big fp16 GEMM: BM=256, BN=64, 8 warps 4(m)x2(n), warp tile 64x32
// =============================================================================
__global__ __launch_bounds__(GT) void gemm_h16big(
    const __half* __restrict__ A0, const __half* __restrict__ W0,
    const float* __restrict__ bias, __half* __restrict__ Ch,
    int ldc, int Ntot, int K)
{
    const int tid  = threadIdx.x;
    const int lane = tid & 31;
    const int warp = tid >> 5;
    const int wm   = warp & 3;
    const int wn   = warp >> 2;
    const int n0   = blockIdx.x * BN;
    const int m0   = blockIdx.y * BM2;

    const uint32_t sbase = smem_u32(smem_raw);
    const int ktotal = K / 64;

    auto load_stage = [&](int l) {
        const int s  = l % STAGES;
        const int kk = l * 64;
        const uint32_t abase = sbase + s * STAGE_BYTES2;
        const uint32_t bbase = abase + A_STAGE2;
        #pragma unroll
        for (int i = 0; i < 8; i++) {                 // 2048 chunks
            int q = tid + i * GT;
            int row = q >> 3, c = q & 7;
            cp16(abase + row * 128 + ((c ^ (row & 7)) << 4),
                 A0 + (size_t)(m0 + row) * K + kk + c * 8);
        }
        #pragma unroll
        for (int i = 0; i < 2; i++) {                 // 512 chunks
            int q = tid + i * GT;
            int row = q >> 3, c = q & 7;
            int gr = n0 + row;
            const __half* src; int sz;
            if (gr < Ntot) { src = W0 + (size_t)gr * K + kk + c * 8; sz = 16; }
            else           { src = W0;                               sz = 0;  }
            cp16z(bbase + row * 128 + ((c ^ (row & 7)) << 4), src, sz);
        }
        asm volatile("cp.async.commit_group;" ::: "memory");
    };

    float acc[4][4][4] = {};
    const int laneRow = lane & 7;
    const int m8      = (lane >> 3) & 1;
    const int cAdd    = lane >> 4;
    uint32_t aOff[4];
    #pragma unroll
    for (int f = 0; f < 4; f++)
        aOff[f] = (uint32_t)(wm * 64 + f * 16 + m8 * 8 + laneRow) * 128;
    const uint32_t bOff = (uint32_t)(wn * 32 + (lane >> 3) * 8 + laneRow) * 128;

    load_stage(0);
    load_stage(1);

    for (int kt = 0; kt < ktotal; ++kt) {
        if (kt + 2 < ktotal) load_stage(kt + 2);
        else asm volatile("cp.async.commit_group;" ::: "memory");
        asm volatile("cp.async.wait_group %0;" :: "n"(STAGES - 1));
        __syncthreads();

        const uint32_t abase = sbase + (kt % STAGES) * STAGE_BYTES2;
        const uint32_t bbase = abase + A_STAGE2;
        #pragma unroll
        for (int ks = 0; ks < 4; ++ks) {
            uint32_t a[4][4], b0[4], b1[4];
            uint32_t aSw = (uint32_t)(((2 * ks + cAdd) ^ laneRow) << 4);
            LDSM4(b0, bbase + bOff + (uint32_t)(((2 * ks)     ^ laneRow) << 4));
            LDSM4(b1, bbase + bOff + (uint32_t)(((2 * ks + 1) ^ laneRow) << 4));
            #pragma unroll
            for (int f = 0; f < 4; f++) LDSM4(a[f], abase + aOff[f] + aSw);
            #pragma unroll
            for (int f = 0; f < 4; f++)
                #pragma unroll
                for (int j = 0; j < 4; j++)
                    MMA16816(acc[f][j], a[f], b0[j], b1[j]);
        }
        __syncthreads();
    }

    float* Cst = (float*)smem_raw;
    #pragma unroll
    for (int f = 0; f < 4; f++)
        #pragma unroll
        for (int j = 0; j < 4; j++) {
            int r0 = wm * 64 + f * 16 + (lane >> 2);
            int c0 = wn * 32 + j * 8 + (lane & 3) * 2;
            Cst[r0 * CLD + c0]           = acc[f][j][0];
            Cst[r0 * CLD + c0 + 1]       = acc[f][j][1];
            Cst[(r0 + 8) * CLD + c0]     = acc[f][j][2];
            Cst[(r0 + 8) * CLD + c0 + 1] = acc[f][j][3];
        }
    __syncthreads();

    for (int idx = tid; idx < BM2 * BN; idx += GT) {
        int r = idx >> 6, c = idx & 63, gc = n0 + c;
        if (gc < Ntot)
            Ch[(size_t)(m0 + r) * ldc + gc] =
                __float2half(Cst[r * CLD + c] + bias[gc]);
    }
}

// ---------------- mega convert: all f32 sources -> fp16 arena ----------------
__global__ __launch_bounds__(256) void convert_all(
    const float* __restrict__ att, const float* __restrict__ x,
    const float* __restrict__ ph,
    const float* __restrict__ wa2a, const float* __restrict__ wa2a1,
    const float* __restrict__ wh2a, const float* __restrict__ wh2a1,
    const float* __restrict__ wi,   const float* __restrict__ wh,
    const float* __restrict__ wa,   __half* __restrict__ buf)
{
    // segment table in float4 units
    const size_t e0 = SZ_ATT / 4;                 // att
    const size_t e1 = e0 + SZ_BV / 4;             // x
    const size_t e2 = e1 + SZ_BV / 4;             // prev_h
    const size_t e3 = e2 + SZ_WATT / 4;           // W_a2a
    const size_t e4 = e3 + SZ_WATT / 4;           // W_a2a1
    const size_t e5 = e4 + SZ_WATT / 4;           // W_h2a
    const size_t e6 = e5 + SZ_WATT / 4;           // W_h2a1
    const size_t e7 = e6 + SZ_WL / 4;             // W_i2h
    const size_t e8 = e7 + SZ_WL / 4;             // W_h2h
    const size_t e9 = e8 + SZ_WL / 4;             // W_a2h

    size_t i = (size_t)blockIdx.x * blockDim.x + threadIdx.x;
    if (i >= e9) return;

    const float* src; size_t rel; size_t dofs;
    if      (i < e0) { src = att;   rel = i;      dofs = OFF_ATT; }
    else if (i < e1) { src = x;     rel = i - e0; dofs = OFF_X; }
    else if (i < e2) { src = ph;    rel = i - e1; dofs = OFF_PH; }
    else if (i < e3) { src = wa2a;  rel = i - e2; dofs = OFF_WBIG; }
    else if (i < e4) { src = wa2a1; rel = i - e3; dofs = OFF_WBIG + SZ_WATT; }
    else if (i < e5) { src = wh2a;  rel = i - e4; dofs = OFF_WH2A; }
    else if (i < e6) { src = wh2a1; rel = i - e5; dofs = OFF_WH2A1; }
    else if (i < e7) { src = wi;    rel = i - e6; dofs = OFF_WI2H; }
    else if (i < e8) { src = wh;    rel = i - e7; dofs = OFF_WH2H; }
    else             { src = wa;    rel = i - e8; dofs = OFF_WA2H; }

    float4 v = ((const float4*)src)[rel];
    __half2 h0 = __floats2half2_rn(v.x, v.y);
    __half2 h1 = __floats2half2_rn(v.z, v.w);
    ((__half2*)(buf + dofs))[2 * rel]     = h0;
    ((__half2*)(buf + dofs))[2 * rel + 1] = h1;
}

// ---------------- fused biases -----------------------------------------------
__global__ void bias_fuse_kernel(
    const float* __restrict__ ba, const float* __restrict__ ba1,
    const float* __restrict__ bi, const float* __restrict__ bh,
    const float* __restrict__ bg,
    float* __restrict__ bbig, float* __restrict__ blstm)
{
    int t = blockIdx.x * blockDim.x + threadIdx.x;
    if (t < ATT_)       bbig[t] = ba[t];
    else if (t < NBIG)  bbig[t] = ba1[t - ATT_];
    int u = t - 512;
    if (u >= 0 && u < 4 * RNN_) blstm[u] = bi[u] + bh[u] + bg[u];
}

// ---------------- dot[m] = bd + sum_j Wd[j]*tanh(V[m,j] + ah[m]) -------------
__global__ __launch_bounds__(256) void reduce_dot_kernel(
    const __half* __restrict__ V, int ldv, const float* __restrict__ ah,
    const float* __restrict__ Wd, const float* __restrict__ bd,
    float* __restrict__ dotv, int Mrows)
{
    int m    = (blockIdx.x * blockDim.x + threadIdx.x) >> 5;
    int lane = threadIdx.x & 31;
    if (m >= Mrows) return;
    float ahm = ah[m];
    const __half* vr = V + (size_t)m * ldv;
    float s = 0.f;
    #pragma unroll 2
    for (int j = lane; j < ATT_; j += 32)
        s += Wd[j] * tanh_s(__half2float(vr[j]) + ahm);
    #pragma unroll
    for (int o = 16; o; o >>= 1) s += __shfl_down_sync(0xffffffffu, s, o);
    if (lane == 0) dotv[m] = s + bd[0];
}

// ---------------- softmax over ATT per batch row -----------------------------
__global__ __launch_bounds__(256) void softmax_kernel(
    const float* __restrict__ dotv, float* __restrict__ w)
{
    int b = blockIdx.x;
    int t = threadIdx.x;
    __shared__ float sd[256];
    float v = (t < ATT_) ? dotv[b * ATT_ + t] : -1e30f;
    sd[t] = v; __syncthreads();
    #pragma unroll
    for (int s = 128; s; s >>= 1) { if (t < s) sd[t] = fmaxf(sd[t], sd[t + s]); __syncthreads(); }
    float mx = sd[0]; __syncthreads();
    float e = (t < ATT_) ? expf(v - mx) : 0.f;
    sd[t] = e; __syncthreads();
    #pragma unroll
    for (int s = 128; s; s >>= 1) { if (t < s) sd[t] += sd[t + s]; __syncthreads(); }
    float inv = 1.0f / sd[0];
    if (t < ATT_) w[b * ATT_ + t] = e * inv;
}

// ---------------- att_res: fp16 out (outH) or f32 out (outF, + addend) -------
__global__ __launch_bounds__(128) void attres_kernel(
    const __half* __restrict__ attH, const float* __restrict__ w,
    const float* __restrict__ addend, float* __restrict__ outF,
    __half* __restrict__ outH)
{
    int b = blockIdx.x;
    int t = threadIdx.x;
    __shared__ float ws[ATT_];
    for (int a = t; a < ATT_; a += 128) ws[a] = w[b * ATT_ + a];
    __syncthreads();
    int col = t * 8;
    const uint4* base = (const uint4*)(attH + (size_t)b * ATT_ * RNN_ + col);
    float s[8] = {};
    #pragma unroll 4
    for (int a = 0; a < ATT_; ++a) {
        uint4 u = base[(size_t)a * (RNN_ / 8)];
        const __half2* hp = (const __half2*)&u;
        float wa = ws[a];
        #pragma unroll
        for (int q = 0; q < 4; q++) {
            float2 f = __half22float2(hp[q]);
            s[2 * q]     += wa * f.x;
            s[2 * q + 1] += wa * f.y;
        }
    }
    if (addend) {
        #pragma unroll
        for (int q = 0; q < 8; q++) s[q] += addend[(size_t)b * RNN_ + col + q];
    }
    if (outF) {
        #pragma unroll
        for (int q = 0; q < 8; q += 4)
            *(float4*)(outF + (size_t)b * RNN_ + col + q) =
                make_float4(s[q], s[q + 1], s[q + 2], s[q + 3]);
    }
    if (outH) {
        __half2 h[4];
        #pragma unroll
        for (int q = 0; q < 4; q++) h[q] = __floats2half2_rn(s[2 * q], s[2 * q + 1]);
        *(uint4*)(outH + (size_t)b * RNN_ + col) = *(uint4*)h;
    }
}

// ---------------- LSTM gates (also emits fp16 next_h) ------------------------
__global__ __launch_bounds__(256) void gates_kernel(
    const float* __restrict__ S, const float* __restrict__ prev_c,
    float* __restrict__ next_c, float* __restrict__ next_h,
    __half* __restrict__ nhH)
{
    int i = blockIdx.x * blockDim.x + threadIdx.x;
    int b = i >> 10, n = i & 1023;
    const float* s = S + (size_t)b * 4 * RNN_;
    float si = s[n];
    float sf = s[RNN_ + n];
    float so = s[2 * RNN_ + n];
    float st = s[3 * RNN_ + n];
    float c = sigmoid_s(sf) * prev_c[i] + sigmoid_s(si) * tanh_s(st);
    float h = sigmoid_s(so) * tanh_s(c);
    next_c[i] = c;
    next_h[i] = h;
    nhH[i]    = __float2half(h);
}

// ---------------- launcher ----------------------------------------------------
extern "C" void kernel_launch(void* const* d_in, const int* in_sizes, int n_in,
                              void* d_out, int out_size)
{
    const float* x      = (const float*)d_in[0];
    const float* att    = (const float*)d_in[1];
    const float* prev_h = (const float*)d_in[2];
    const float* prev_c = (const float*)d_in[3];
    const float* W_a2a  = (const float*)d_in[4];
    const float* b_a2a  = (const float*)d_in[5];
    const float* W_h2a  = (const float*)d_in[6];
    const float* b_h2a  = (const float*)d_in[7];
    const float* W_d2d  = (const float*)d_in[8];
    const float* b_d2d  = (const float*)d_in[9];
    const float* W_a2h  = (const float*)d_in[10];
    const float* b_a2h  = (const float*)d_in[11];
    const float* W_i2h  = (const float*)d_in[12];
    const float* b_i2h  = (const float*)d_in[13];
    const float* W_h2h  = (const float*)d_in[14];
    const float* b_h2h  = (const float*)d_in[15];
    const float* W_a2a1 = (const float*)d_in[16];
    const float* b_a2a1 = (const float*)d_in[17];
    const float* W_h2a1 = (const float*)d_in[18];
    const float* b_h2a1 = (const float*)d_in[19];
    const float* W_d2d1 = (const float*)d_in[20];
    const float* b_d2d1 = (const float*)d_in[21];

    float* out    = (float*)d_out;
    float* next_c = out;
    float* next_h = out + (size_t)B_ * RNN_;
    float* top_h  = out + (size_t)2 * B_ * RNN_;

    __half* H; __half* V;
    float *bbig, *blstm, *ah1, *ah2, *dotv, *w1, *w2, *S;
    cudaGetSymbolAddress((void**)&H,     g_h);
    cudaGetSymbolAddress((void**)&V,     g_V);
    cudaGetSymbolAddress((void**)&bbig,  g_bbig);
    cudaGetSymbolAddress((void**)&blstm, g_blstm);
    cudaGetSymbolAddress((void**)&ah1,   g_ah1);
    cudaGetSymbolAddress((void**)&ah2,   g_ah2);
    cudaGetSymbolAddress((void**)&dotv,  g_dot);
    cudaGetSymbolAddress((void**)&w1,    g_w1);
    cudaGetSymbolAddress((void**)&w2,    g_w2);
    cudaGetSymbolAddress((void**)&S,     g_S);

    cudaFuncSetAttribute(gemm_h16,    cudaFuncAttributeMaxDynamicSharedMemorySize, GEMM_SMEM);
    cudaFuncSetAttribute(gemm_h16big, cudaFuncAttributeMaxDynamicSharedMemorySize, GEMM_SMEM2);

    const int Mbig = B_ * ATT_;   // 50176
    const size_t CV_TOT = (OFF_ARES1) / 4;   // float4 count of converted region

    // 1) converts + biases (2 launches)
    convert_all<<<(unsigned)((CV_TOT + 255) / 256), 256>>>(
        att, x, prev_h, W_a2a, W_a2a1, W_h2a, W_h2a1, W_i2h, W_h2h, W_a2h, H);
    bias_fuse_kernel<<<(512 + 4 * RNN_ + 255) / 256, 256>>>(
        b_a2a, b_a2a1, b_i2h, b_h2h, b_a2h, bbig, blstm);

    // 2) fused big attention GEMM: V[:,0:392] = attH @ [Wa2a|Wa2a1]^T
    gemm_h16big<<<dim3(7, Mbig / BM2), GT, GEMM_SMEM2>>>(
        H + OFF_ATT, H + OFF_WBIG, bbig, V, NBIG, NBIG, RNN_);

    // 3) ah1 = prev_h @ W_h2a^T
    gemm_h16<<<dim3(4, B_ / BM), GT, GEMM_SMEM>>>(
        H + OFF_PH, nullptr, nullptr, H + OFF_WH2A, nullptr, nullptr,
        b_h2a, nullptr, ah1, ATT_, ATT_, RNN_, 1);

    // 4) attend 1 (ares -> fp16 directly)
    reduce_dot_kernel<<<Mbig / 8, 256>>>(V, NBIG, ah1, W_d2d, b_d2d, dotv, Mbig);
    softmax_kernel<<<B_, 256>>>(dotv, w1);
    attres_kernel<<<B_, 128>>>(H + OFF_ATT, w1, nullptr, nullptr, H + OFF_ARES1);

    // 5) fused LSTM: S = xH@Wi^T + phH@Wh^T + ares1H@Wa^T + blstm
    gemm_h16<<<dim3(64, B_ / BM), GT, GEMM_SMEM>>>(
        H + OFF_X, H + OFF_PH, H + OFF_ARES1,
        H + OFF_WI2H, H + OFF_WH2H, H + OFF_WA2H,
        blstm, nullptr, S, 4 * RNN_, 4 * RNN_, RNN_, 3);

    gates_kernel<<<(B_ * RNN_) / 256, 256>>>(S, prev_c, next_c, next_h, H + OFF_NH);

    // 6) attend 2 (on next_h)
    gemm_h16<<<dim3(4, B_ / BM), GT, GEMM_SMEM>>>(
        H + OFF_NH, nullptr, nullptr, H + OFF_WH2A1, nullptr, nullptr,
        b_h2a1, nullptr, ah2, ATT_, ATT_, RNN_, 1);

    reduce_dot_kernel<<<Mbig / 8, 256>>>(V + ATT_, NBIG, ah2, W_d2d1, b_d2d1, dotv, Mbig);
    softmax_kernel<<<B_, 256>>>(dotv, w2);
    attres_kernel<<<B_, 128>>>(H + OFF_ATT, w2, next_h, top_h, nullptr);
}